// round 2
// baseline (speedup 1.0000x reference)
#include <cuda_runtime.h>
#include <math.h>

#define B_   2
#define SEQ  1024
#define DIM_ 2048
#define KVD  512
#define NH   32
#define NKV  8
#define HD   64

// Scratch (allocation-guard-safe __device__ globals, ~40MB)
__device__ float g_q[B_ * SEQ * DIM_];
__device__ float g_k[B_ * SEQ * KVD];
__device__ float g_v[B_ * SEQ * KVD];
__device__ float g_att[B_ * SEQ * DIM_];

// ---------------------------------------------------------------------------
// Generic fp32 GEMM: C[M,N] = A[M,K] @ B[K,N], all row-major.
// 128x128 block tile, BK=16, 256 threads, 8x8 register microtile.
// Requires M%128==0, N%128==0, K%16==0 (true for all our shapes).
// ---------------------------------------------------------------------------
__global__ __launch_bounds__(256)
void gemm128(const float* __restrict__ A, const float* __restrict__ Bm,
             float* __restrict__ C, int M, int N, int K) {
    __shared__ float As[16][128];   // transposed: As[k][m]
    __shared__ float Bs[16][128];   // Bs[k][n]

    const int tid = threadIdx.x;
    const int m0 = blockIdx.y * 128;
    const int n0 = blockIdx.x * 128;

    // compute coords: 16x16 thread grid, 8x8 microtile each
    const int ty = tid >> 4;     // 0..15
    const int tx = tid & 15;     // 0..15

    // A-load coords: 128 rows, 2 threads/row, each loads 8 floats (2x float4)
    const int arow  = tid >> 1;          // 0..127
    const int acol0 = (tid & 1) * 8;     // 0 or 8
    // B-load coords: 16 rows, 16 threads/row, each loads 8 floats
    const int brow  = tid >> 4;          // 0..15
    const int bcol0 = (tid & 15) * 8;

    float acc[8][8];
    #pragma unroll
    for (int i = 0; i < 8; i++)
        #pragma unroll
        for (int j = 0; j < 8; j++) acc[i][j] = 0.0f;

    for (int k0 = 0; k0 < K; k0 += 16) {
        // load A tile (transposed into As[k][m])
        float4 a0 = *(const float4*)&A[(m0 + arow) * K + k0 + acol0];
        float4 a1 = *(const float4*)&A[(m0 + arow) * K + k0 + acol0 + 4];
        As[acol0 + 0][arow] = a0.x; As[acol0 + 1][arow] = a0.y;
        As[acol0 + 2][arow] = a0.z; As[acol0 + 3][arow] = a0.w;
        As[acol0 + 4][arow] = a1.x; As[acol0 + 5][arow] = a1.y;
        As[acol0 + 6][arow] = a1.z; As[acol0 + 7][arow] = a1.w;
        // load B tile
        *(float4*)&Bs[brow][bcol0]     = *(const float4*)&Bm[(k0 + brow) * N + n0 + bcol0];
        *(float4*)&Bs[brow][bcol0 + 4] = *(const float4*)&Bm[(k0 + brow) * N + n0 + bcol0 + 4];
        __syncthreads();

        #pragma unroll
        for (int kk = 0; kk < 16; kk++) {
            float a[8], b[8];
            float4 va0 = *(const float4*)&As[kk][ty * 8];
            float4 va1 = *(const float4*)&As[kk][ty * 8 + 4];
            float4 vb0 = *(const float4*)&Bs[kk][tx * 8];
            float4 vb1 = *(const float4*)&Bs[kk][tx * 8 + 4];
            a[0]=va0.x; a[1]=va0.y; a[2]=va0.z; a[3]=va0.w;
            a[4]=va1.x; a[5]=va1.y; a[6]=va1.z; a[7]=va1.w;
            b[0]=vb0.x; b[1]=vb0.y; b[2]=vb0.z; b[3]=vb0.w;
            b[4]=vb1.x; b[5]=vb1.y; b[6]=vb1.z; b[7]=vb1.w;
            #pragma unroll
            for (int i = 0; i < 8; i++)
                #pragma unroll
                for (int j = 0; j < 8; j++)
                    acc[i][j] = fmaf(a[i], b[j], acc[i][j]);
        }
        __syncthreads();
    }

    // store
    #pragma unroll
    for (int i = 0; i < 8; i++) {
        float* cp = &C[(m0 + ty * 8 + i) * N + n0 + tx * 8];
        float4 v0 = make_float4(acc[i][0], acc[i][1], acc[i][2], acc[i][3]);
        float4 v1 = make_float4(acc[i][4], acc[i][5], acc[i][6], acc[i][7]);
        *(float4*)cp       = v0;
        *(float4*)(cp + 4) = v1;
    }
}

// ---------------------------------------------------------------------------
// RoPE (interleaved pairs) in-place over [B_*SEQ, width] rows;
// width = NH*HD for q, NKV*HD for k. Pair (2i, 2i+1) within each head,
// freq_i = theta^(-i/32), phase = n * freq_i.
// ---------------------------------------------------------------------------
__global__ void rope_kernel(float* __restrict__ x, int width) {
    const int pairsPerRow = width >> 1;
    int idx = blockIdx.x * blockDim.x + threadIdx.x;
    int total = B_ * SEQ * pairsPerRow;
    if (idx >= total) return;
    int row = idx / pairsPerRow;
    int p   = idx - row * pairsPerRow;
    int n   = row & (SEQ - 1);
    int i   = p & 31;   // pair index within head (HD/2 = 32)
    // freq = 10000^(-i/32)
    float freq = expf(-(float)i * (9.2103403719761836f / 32.0f)); // ln(10000)
    float ph = (float)n * freq;
    float sn, cs;
    sincosf(ph, &sn, &cs);
    float* base = x + (size_t)row * width + 2 * p;
    float x0 = base[0], x1 = base[1];
    base[0] = x0 * cs - x1 * sn;
    base[1] = x0 * sn + x1 * cs;
}

// ---------------------------------------------------------------------------
// Flash-style causal attention with GQA (4 q heads per kv head).
// grid: (SEQ/128, NH, B_), block 128. Thread t handles query row
// qi = blockIdx.x*128 + t. K/V staged in smem 64 rows at a time.
// ---------------------------------------------------------------------------
__global__ __launch_bounds__(128)
void flash_kernel(const float* __restrict__ q, const float* __restrict__ k,
                  const float* __restrict__ v, float* __restrict__ o) {
    __shared__ float Ks[64][64];
    __shared__ float Vs[64][64];

    const int tid = threadIdx.x;
    const int b = blockIdx.z;
    const int h = blockIdx.y;
    const int kvh = h >> 2;                 // H/J = 4
    const int qi = blockIdx.x * 128 + tid;

    const float* qp = q + (((size_t)b * SEQ + qi) * NH + h) * HD;
    float qreg[64];
    #pragma unroll
    for (int d = 0; d < 64; d += 4) {
        float4 t = *(const float4*)&qp[d];
        qreg[d] = t.x; qreg[d+1] = t.y; qreg[d+2] = t.z; qreg[d+3] = t.w;
    }

    float m = -INFINITY, l = 0.0f;
    float accv[64];
    #pragma unroll
    for (int d = 0; d < 64; d++) accv[d] = 0.0f;

    const int jt_max = blockIdx.x * 2 + 1;  // last 64-key tile touching this block
    const int lr    = tid >> 1;             // 0..63  (row to load)
    const int lcol  = (tid & 1) * 32;       // column half

    for (int jt = 0; jt <= jt_max; jt++) {
        const size_t krow = ((size_t)b * SEQ + jt * 64 + lr) * NKV + kvh;
        const float* kp = k + krow * HD + lcol;
        const float* vp = v + krow * HD + lcol;
        #pragma unroll
        for (int c = 0; c < 32; c += 4) {
            *(float4*)&Ks[lr][lcol + c] = *(const float4*)&kp[c];
            *(float4*)&Vs[lr][lcol + c] = *(const float4*)&vp[c];
        }
        __syncthreads();

        int jmax = qi - jt * 64;
        if (jmax > 63) jmax = 63;
        for (int j = 0; j <= jmax; j++) {
            float s0 = 0.f, s1 = 0.f, s2 = 0.f, s3 = 0.f;
            #pragma unroll
            for (int d = 0; d < 64; d += 4) {
                s0 = fmaf(qreg[d],     Ks[j][d],     s0);
                s1 = fmaf(qreg[d + 1], Ks[j][d + 1], s1);
                s2 = fmaf(qreg[d + 2], Ks[j][d + 2], s2);
                s3 = fmaf(qreg[d + 3], Ks[j][d + 3], s3);
            }
            float s = ((s0 + s1) + (s2 + s3)) * 0.125f;   // 1/sqrt(64)

            float m_new = fmaxf(m, s);
            float corr  = __expf(m - m_new);
            float p     = __expf(s - m_new);
            l = l * corr + p;
            #pragma unroll
            for (int d = 0; d < 64; d++)
                accv[d] = fmaf(accv[d], corr, p * Vs[j][d]);
            m = m_new;
        }
        __syncthreads();
    }

    const float inv = 1.0f / l;
    float* op = o + (((size_t)b * SEQ + qi) * NH + h) * HD;
    #pragma unroll
    for (int d = 0; d < 64; d += 4) {
        float4 t = make_float4(accv[d] * inv, accv[d+1] * inv,
                               accv[d+2] * inv, accv[d+3] * inv);
        *(float4*)&op[d] = t;
    }
}

// ---------------------------------------------------------------------------
extern "C" void kernel_launch(void* const* d_in, const int* in_sizes, int n_in,
                              void* d_out, int out_size) {
    const float* x  = (const float*)d_in[0];
    const float* wq = (const float*)d_in[1];
    const float* wk = (const float*)d_in[2];
    const float* wv = (const float*)d_in[3];
    const float* wo = (const float*)d_in[4];
    float* out = (float*)d_out;

    float *qb, *kb, *vb, *ab;
    cudaGetSymbolAddress((void**)&qb, g_q);
    cudaGetSymbolAddress((void**)&kb, g_k);
    cudaGetSymbolAddress((void**)&vb, g_v);
    cudaGetSymbolAddress((void**)&ab, g_att);

    const int M = B_ * SEQ;   // 2048

    // QKV projections
    gemm128<<<dim3(DIM_ / 128, M / 128), 256>>>(x, wq, qb, M, DIM_, DIM_);
    gemm128<<<dim3(KVD  / 128, M / 128), 256>>>(x, wk, kb, M, KVD,  DIM_);
    gemm128<<<dim3(KVD  / 128, M / 128), 256>>>(x, wv, vb, M, KVD,  DIM_);

    // RoPE on q and k
    {
        int totq = M * (DIM_ / 2);
        rope_kernel<<<(totq + 255) / 256, 256>>>(qb, DIM_);
        int totk = M * (KVD / 2);
        rope_kernel<<<(totk + 255) / 256, 256>>>(kb, KVD);
    }

    // Causal GQA attention
    flash_kernel<<<dim3(SEQ / 128, NH, B_), 128>>>(qb, kb, vb, ab);

    // Output projection
    gemm128<<<dim3(DIM_ / 128, M / 128), 256>>>(ab, wo, out, M, DIM_, DIM_);
}

// round 3
// speedup vs baseline: 1.0007x; 1.0007x over previous
#include <cuda_runtime.h>
#include <math.h>

#define B_   2
#define SEQ  1024
#define DIM_ 2048
#define KVD  512
#define NH   32
#define NKV  8
#define HD   64

// Scratch (allocation-guard-safe __device__ globals, ~40MB)
__device__ float g_q[B_ * SEQ * DIM_];
__device__ float g_k[B_ * SEQ * KVD];
__device__ float g_v[B_ * SEQ * KVD];
__device__ float g_att[B_ * SEQ * DIM_];

// ---------------------------------------------------------------------------
// Generic fp32 GEMM: C[M,N] = A[M,K] @ B[K,N], all row-major.
// 128x128 block tile, BK=16, 256 threads, 8x8 register microtile.
// Requires M%128==0, N%128==0, K%16==0 (true for all our shapes).
// ---------------------------------------------------------------------------
__global__ __launch_bounds__(256)
void gemm128(const float* __restrict__ A, const float* __restrict__ Bm,
             float* __restrict__ C, int M, int N, int K) {
    __shared__ float As[16][128];   // transposed: As[k][m]
    __shared__ float Bs[16][128];   // Bs[k][n]

    const int tid = threadIdx.x;
    const int m0 = blockIdx.y * 128;
    const int n0 = blockIdx.x * 128;

    // compute coords: 16x16 thread grid, 8x8 microtile each
    const int ty = tid >> 4;     // 0..15
    const int tx = tid & 15;     // 0..15

    // A-load coords: 128 rows, 2 threads/row, each loads 8 floats (2x float4)
    const int arow  = tid >> 1;          // 0..127
    const int acol0 = (tid & 1) * 8;     // 0 or 8
    // B-load coords: 16 rows, 16 threads/row, each loads 8 floats
    const int brow  = tid >> 4;          // 0..15
    const int bcol0 = (tid & 15) * 8;

    float acc[8][8];
    #pragma unroll
    for (int i = 0; i < 8; i++)
        #pragma unroll
        for (int j = 0; j < 8; j++) acc[i][j] = 0.0f;

    for (int k0 = 0; k0 < K; k0 += 16) {
        // load A tile (transposed into As[k][m])
        float4 a0 = *(const float4*)&A[(m0 + arow) * K + k0 + acol0];
        float4 a1 = *(const float4*)&A[(m0 + arow) * K + k0 + acol0 + 4];
        As[acol0 + 0][arow] = a0.x; As[acol0 + 1][arow] = a0.y;
        As[acol0 + 2][arow] = a0.z; As[acol0 + 3][arow] = a0.w;
        As[acol0 + 4][arow] = a1.x; As[acol0 + 5][arow] = a1.y;
        As[acol0 + 6][arow] = a1.z; As[acol0 + 7][arow] = a1.w;
        // load B tile
        *(float4*)&Bs[brow][bcol0]     = *(const float4*)&Bm[(k0 + brow) * N + n0 + bcol0];
        *(float4*)&Bs[brow][bcol0 + 4] = *(const float4*)&Bm[(k0 + brow) * N + n0 + bcol0 + 4];
        __syncthreads();

        #pragma unroll
        for (int kk = 0; kk < 16; kk++) {
            float a[8], b[8];
            float4 va0 = *(const float4*)&As[kk][ty * 8];
            float4 va1 = *(const float4*)&As[kk][ty * 8 + 4];
            float4 vb0 = *(const float4*)&Bs[kk][tx * 8];
            float4 vb1 = *(const float4*)&Bs[kk][tx * 8 + 4];
            a[0]=va0.x; a[1]=va0.y; a[2]=va0.z; a[3]=va0.w;
            a[4]=va1.x; a[5]=va1.y; a[6]=va1.z; a[7]=va1.w;
            b[0]=vb0.x; b[1]=vb0.y; b[2]=vb0.z; b[3]=vb0.w;
            b[4]=vb1.x; b[5]=vb1.y; b[6]=vb1.z; b[7]=vb1.w;
            #pragma unroll
            for (int i = 0; i < 8; i++)
                #pragma unroll
                for (int j = 0; j < 8; j++)
                    acc[i][j] = fmaf(a[i], b[j], acc[i][j]);
        }
        __syncthreads();
    }

    // store
    #pragma unroll
    for (int i = 0; i < 8; i++) {
        float* cp = &C[(m0 + ty * 8 + i) * N + n0 + tx * 8];
        float4 v0 = make_float4(acc[i][0], acc[i][1], acc[i][2], acc[i][3]);
        float4 v1 = make_float4(acc[i][4], acc[i][5], acc[i][6], acc[i][7]);
        *(float4*)cp       = v0;
        *(float4*)(cp + 4) = v1;
    }
}

// ---------------------------------------------------------------------------
// RoPE (interleaved pairs) in-place over [B_*SEQ, width] rows;
// width = NH*HD for q, NKV*HD for k. Pair (2i, 2i+1) within each head,
// freq_i = theta^(-i/32), phase = n * freq_i.
// ---------------------------------------------------------------------------
__global__ void rope_kernel(float* __restrict__ x, int width) {
    const int pairsPerRow = width >> 1;
    int idx = blockIdx.x * blockDim.x + threadIdx.x;
    int total = B_ * SEQ * pairsPerRow;
    if (idx >= total) return;
    int row = idx / pairsPerRow;
    int p   = idx - row * pairsPerRow;
    int n   = row & (SEQ - 1);
    int i   = p & 31;   // pair index within head (HD/2 = 32)
    // freq = 10000^(-i/32)
    float freq = expf(-(float)i * (9.2103403719761836f / 32.0f)); // ln(10000)
    float ph = (float)n * freq;
    float sn, cs;
    sincosf(ph, &sn, &cs);
    float* base = x + (size_t)row * width + 2 * p;
    float x0 = base[0], x1 = base[1];
    base[0] = x0 * cs - x1 * sn;
    base[1] = x0 * sn + x1 * cs;
}

// ---------------------------------------------------------------------------
// Flash-style causal attention with GQA (4 q heads per kv head).
// grid: (SEQ/128, NH, B_), block 128. Thread t handles query row
// qi = blockIdx.x*128 + t. K/V staged in smem 64 rows at a time.
// ---------------------------------------------------------------------------
__global__ __launch_bounds__(128)
void flash_kernel(const float* __restrict__ q, const float* __restrict__ k,
                  const float* __restrict__ v, float* __restrict__ o) {
    __shared__ float Ks[64][64];
    __shared__ float Vs[64][64];

    const int tid = threadIdx.x;
    const int b = blockIdx.z;
    const int h = blockIdx.y;
    const int kvh = h >> 2;                 // H/J = 4
    const int qi = blockIdx.x * 128 + tid;

    const float* qp = q + (((size_t)b * SEQ + qi) * NH + h) * HD;
    float qreg[64];
    #pragma unroll
    for (int d = 0; d < 64; d += 4) {
        float4 t = *(const float4*)&qp[d];
        qreg[d] = t.x; qreg[d+1] = t.y; qreg[d+2] = t.z; qreg[d+3] = t.w;
    }

    float m = -INFINITY, l = 0.0f;
    float accv[64];
    #pragma unroll
    for (int d = 0; d < 64; d++) accv[d] = 0.0f;

    const int jt_max = blockIdx.x * 2 + 1;  // last 64-key tile touching this block
    const int lr    = tid >> 1;             // 0..63  (row to load)
    const int lcol  = (tid & 1) * 32;       // column half

    for (int jt = 0; jt <= jt_max; jt++) {
        const size_t krow = ((size_t)b * SEQ + jt * 64 + lr) * NKV + kvh;
        const float* kp = k + krow * HD + lcol;
        const float* vp = v + krow * HD + lcol;
        #pragma unroll
        for (int c = 0; c < 32; c += 4) {
            *(float4*)&Ks[lr][lcol + c] = *(const float4*)&kp[c];
            *(float4*)&Vs[lr][lcol + c] = *(const float4*)&vp[c];
        }
        __syncthreads();

        int jmax = qi - jt * 64;
        if (jmax > 63) jmax = 63;
        for (int j = 0; j <= jmax; j++) {
            float s0 = 0.f, s1 = 0.f, s2 = 0.f, s3 = 0.f;
            #pragma unroll
            for (int d = 0; d < 64; d += 4) {
                s0 = fmaf(qreg[d],     Ks[j][d],     s0);
                s1 = fmaf(qreg[d + 1], Ks[j][d + 1], s1);
                s2 = fmaf(qreg[d + 2], Ks[j][d + 2], s2);
                s3 = fmaf(qreg[d + 3], Ks[j][d + 3], s3);
            }
            float s = ((s0 + s1) + (s2 + s3)) * 0.125f;   // 1/sqrt(64)

            float m_new = fmaxf(m, s);
            float corr  = __expf(m - m_new);
            float p     = __expf(s - m_new);
            l = l * corr + p;
            #pragma unroll
            for (int d = 0; d < 64; d++)
                accv[d] = fmaf(accv[d], corr, p * Vs[j][d]);
            m = m_new;
        }
        __syncthreads();
    }

    const float inv = 1.0f / l;
    float* op = o + (((size_t)b * SEQ + qi) * NH + h) * HD;
    #pragma unroll
    for (int d = 0; d < 64; d += 4) {
        float4 t = make_float4(accv[d] * inv, accv[d+1] * inv,
                               accv[d+2] * inv, accv[d+3] * inv);
        *(float4*)&op[d] = t;
    }
}

// ---------------------------------------------------------------------------
extern "C" void kernel_launch(void* const* d_in, const int* in_sizes, int n_in,
                              void* d_out, int out_size) {
    const float* x  = (const float*)d_in[0];
    const float* wq = (const float*)d_in[1];
    const float* wk = (const float*)d_in[2];
    const float* wv = (const float*)d_in[3];
    const float* wo = (const float*)d_in[4];
    float* out = (float*)d_out;

    float *qb, *kb, *vb, *ab;
    cudaGetSymbolAddress((void**)&qb, g_q);
    cudaGetSymbolAddress((void**)&kb, g_k);
    cudaGetSymbolAddress((void**)&vb, g_v);
    cudaGetSymbolAddress((void**)&ab, g_att);

    const int M = B_ * SEQ;   // 2048

    // QKV projections
    gemm128<<<dim3(DIM_ / 128, M / 128), 256>>>(x, wq, qb, M, DIM_, DIM_);
    gemm128<<<dim3(KVD  / 128, M / 128), 256>>>(x, wk, kb, M, KVD,  DIM_);
    gemm128<<<dim3(KVD  / 128, M / 128), 256>>>(x, wv, vb, M, KVD,  DIM_);

    // RoPE on q and k
    {
        int totq = M * (DIM_ / 2);
        rope_kernel<<<(totq + 255) / 256, 256>>>(qb, DIM_);
        int totk = M * (KVD / 2);
        rope_kernel<<<(totk + 255) / 256, 256>>>(kb, KVD);
    }

    // Causal GQA attention
    flash_kernel<<<dim3(SEQ / 128, NH, B_), 128>>>(qb, kb, vb, ab);

    // Output projection
    gemm128<<<dim3(DIM_ / 128, M / 128), 256>>>(ab, wo, out, M, DIM_, DIM_);
}

// round 5
// speedup vs baseline: 1.6794x; 1.6783x over previous
#include <cuda_runtime.h>
#include <cuda_bf16.h>
#include <math.h>
#include <stdint.h>

#define B_   2
#define SEQ  1024
#define DIM_ 2048
#define KVD  512
#define NH   32
#define NKV  8
#define HD   64
#define MTOT (B_ * SEQ)   // 2048

// ---------------- scratch (__device__ globals; allocation-guard safe) ------
__device__ float g_q[MTOT * DIM_];
__device__ float g_k[MTOT * KVD];
__device__ float g_v[MTOT * KVD];
__device__ float g_att[MTOT * DIM_];

__device__ __nv_bfloat16 g_xh[MTOT * DIM_], g_xl[MTOT * DIM_];
__device__ __nv_bfloat16 g_ah[MTOT * DIM_], g_al[MTOT * DIM_];
// weights transposed to [N, K] row-major, split hi/lo
__device__ __nv_bfloat16 g_wqh[DIM_ * DIM_], g_wql[DIM_ * DIM_];
__device__ __nv_bfloat16 g_wkh[KVD  * DIM_], g_wkl[KVD  * DIM_];
__device__ __nv_bfloat16 g_wvh[KVD  * DIM_], g_wvl[KVD  * DIM_];
__device__ __nv_bfloat16 g_woh[DIM_ * DIM_], g_wol[DIM_ * DIM_];

// ---------------- helpers ---------------------------------------------------
__device__ __forceinline__ uint32_t smem_u32(const void* p) {
    uint32_t a;
    asm("{ .reg .u64 t; cvta.to.shared.u64 t, %1; cvt.u32.u64 %0, t; }"
        : "=r"(a) : "l"(p));
    return a;
}
__device__ __forceinline__ void cp16(uint32_t dst, const void* src) {
    uint64_t g = __cvta_generic_to_global(src);
    asm volatile("cp.async.cg.shared.global [%0], [%1], 16;" :: "r"(dst), "l"(g));
}
__device__ __forceinline__ void ldmx4(uint32_t* r, uint32_t addr) {
    asm volatile("ldmatrix.sync.aligned.m8n8.x4.shared.b16 {%0,%1,%2,%3}, [%4];"
                 : "=r"(r[0]), "=r"(r[1]), "=r"(r[2]), "=r"(r[3]) : "r"(addr));
}
__device__ __forceinline__ void mma16816(float* c, const uint32_t* a, const uint32_t* b) {
    asm volatile(
        "mma.sync.aligned.m16n8k16.row.col.f32.bf16.bf16.f32 "
        "{%0,%1,%2,%3}, {%4,%5,%6,%7}, {%8,%9}, {%0,%1,%2,%3};"
        : "+f"(c[0]), "+f"(c[1]), "+f"(c[2]), "+f"(c[3])
        : "r"(a[0]), "r"(a[1]), "r"(a[2]), "r"(a[3]), "r"(b[0]), "r"(b[1]));
}

// ---------------- conversion kernels ---------------------------------------
__global__ void split_bf16(const float* __restrict__ src,
                           __nv_bfloat16* __restrict__ hi,
                           __nv_bfloat16* __restrict__ lo, int n) {
    int i = blockIdx.x * blockDim.x + threadIdx.x;
    if (i >= n) return;
    float v = src[i];
    __nv_bfloat16 h = __float2bfloat16(v);
    hi[i] = h;
    lo[i] = __float2bfloat16(v - __bfloat162float(h));
}

// W [K,N] row-major -> hi/lo [N,K] row-major
__global__ void transpose_split(const float* __restrict__ W,
                                __nv_bfloat16* __restrict__ hi,
                                __nv_bfloat16* __restrict__ lo, int K, int N) {
    __shared__ float t[32][33];
    int k0 = blockIdx.y * 32, n0 = blockIdx.x * 32;
    int tx = threadIdx.x, ty = threadIdx.y;   // 32 x 8
    #pragma unroll
    for (int r = ty; r < 32; r += 8)
        t[r][tx] = W[(size_t)(k0 + r) * N + n0 + tx];
    __syncthreads();
    #pragma unroll
    for (int r = ty; r < 32; r += 8) {
        float v = t[tx][r];   // W[k0+tx][n0+r]
        __nv_bfloat16 h = __float2bfloat16(v);
        size_t o = (size_t)(n0 + r) * K + k0 + tx;
        hi[o] = h;
        lo[o] = __float2bfloat16(v - __bfloat162float(h));
    }
}

// ---------------- mma.sync bf16 GEMM ----------------------------------------
// C[M,N] = (Ah+Al)[M,K] @ (Bh+Bl)^T with B stored [N,K] row-major.
// 128x128 block tile, BK=32, 256 threads (8 warps, each 32m x 64n).
// SMEM rows padded to 80B (stride 40 bf16) => conflict-free ldmatrix.
#define ROWB       80
#define TILE_B     (128 * ROWB)          // 10240 bytes per operand tile
#define STAGE_B    (4 * TILE_B)          // Ah, Al, Bh, Bl
#define GEMM_SMEM  (2 * STAGE_B)         // double buffer = 81920

__global__ __launch_bounds__(256)
void mma_gemm(const __nv_bfloat16* __restrict__ Ah, const __nv_bfloat16* __restrict__ Al,
              const __nv_bfloat16* __restrict__ Bh, const __nv_bfloat16* __restrict__ Bl,
              float* __restrict__ C, int N, int K) {
    extern __shared__ char sm[];
    const uint32_t sbase = smem_u32(sm);
    const int tid  = threadIdx.x;
    const int wid  = tid >> 5;
    const int lane = tid & 31;
    const int wm = wid & 3;       // 0..3 -> 32-row slice
    const int wn = wid >> 2;      // 0..1 -> 64-col slice
    const int m0 = blockIdx.y * 128, n0 = blockIdx.x * 128;

    float acc[2][8][4];
    #pragma unroll
    for (int i = 0; i < 2; i++)
        #pragma unroll
        for (int j = 0; j < 8; j++)
            #pragma unroll
            for (int q = 0; q < 4; q++) acc[i][j][q] = 0.0f;

    const __nv_bfloat16* base[4] = {
        Ah + (size_t)m0 * K, Al + (size_t)m0 * K,
        Bh + (size_t)n0 * K, Bl + (size_t)n0 * K };

    // per-thread load coords: 2 chunks of 16B per operand tile
    const int r0 = tid >> 2, c0 = tid & 3;               // u = tid
    const int r1 = (tid + 256) >> 2, c1 = tid & 3;       // u = tid + 256

    auto load_stage = [&](int cidx) {
        const int k0 = cidx << 5;
        const uint32_t db = sbase + (uint32_t)(cidx & 1) * STAGE_B;
        #pragma unroll
        for (int t = 0; t < 4; t++) {
            const uint32_t tb = db + t * TILE_B;
            cp16(tb + r0 * ROWB + c0 * 16, base[t] + (size_t)r0 * K + k0 + c0 * 8);
            cp16(tb + r1 * ROWB + c1 * 16, base[t] + (size_t)r1 * K + k0 + c1 * 8);
        }
        asm volatile("cp.async.commit_group;");
    };

    // ldmatrix per-lane address components
    const int aRow  = lane & 15;
    const uint32_t aColb = (uint32_t)(lane >> 4) * 16;
    const int bRow  = ((lane & 16) >> 1) + (lane & 7);
    const uint32_t bColb = (uint32_t)((lane >> 3) & 1) * 16;

    load_stage(0);
    const int NC = K >> 5;
    for (int c = 0; c < NC; c++) {
        if (c + 1 < NC) {
            load_stage(c + 1);
            asm volatile("cp.async.wait_group 1;");
        } else {
            asm volatile("cp.async.wait_group 0;");
        }
        __syncthreads();

        const uint32_t db = sbase + (uint32_t)(c & 1) * STAGE_B;
        #pragma unroll
        for (int ks = 0; ks < 2; ks++) {
            const uint32_t kb = (uint32_t)ks * 32;
            uint32_t ah[2][4], al[2][4];
            #pragma unroll
            for (int mt = 0; mt < 2; mt++) {
                uint32_t addr = db + (uint32_t)(wm * 32 + mt * 16 + aRow) * ROWB + aColb + kb;
                ldmx4(ah[mt], addr);
                ldmx4(al[mt], addr + TILE_B);
            }
            uint32_t bh[4][4], bl[4][4];
            #pragma unroll
            for (int ng = 0; ng < 4; ng++) {
                uint32_t addr = db + 2 * TILE_B +
                                (uint32_t)(wn * 64 + ng * 16 + bRow) * ROWB + bColb + kb;
                ldmx4(bh[ng], addr);
                ldmx4(bl[ng], addr + TILE_B);
            }
            #pragma unroll
            for (int mt = 0; mt < 2; mt++)
                #pragma unroll
                for (int nt = 0; nt < 8; nt++) {
                    const int ng = nt >> 1, hf = (nt & 1) * 2;
                    mma16816(acc[mt][nt], ah[mt], &bh[ng][hf]);
                    mma16816(acc[mt][nt], ah[mt], &bl[ng][hf]);
                    mma16816(acc[mt][nt], al[mt], &bh[ng][hf]);
                }
        }
        __syncthreads();
    }

    // epilogue
    const int g = lane >> 2, tg = lane & 3;
    #pragma unroll
    for (int mt = 0; mt < 2; mt++)
        #pragma unroll
        for (int nt = 0; nt < 8; nt++) {
            const int row = m0 + wm * 32 + mt * 16 + g;
            const int col = n0 + wn * 64 + nt * 8 + tg * 2;
            *(float2*)&C[(size_t)row * N + col] =
                make_float2(acc[mt][nt][0], acc[mt][nt][1]);
            *(float2*)&C[(size_t)(row + 8) * N + col] =
                make_float2(acc[mt][nt][2], acc[mt][nt][3]);
        }
}

// ---------------- RoPE ------------------------------------------------------
__global__ void rope_kernel(float* __restrict__ x, int width) {
    const int pairsPerRow = width >> 1;
    int idx = blockIdx.x * blockDim.x + threadIdx.x;
    int total = B_ * SEQ * pairsPerRow;
    if (idx >= total) return;
    int row = idx / pairsPerRow;
    int p   = idx - row * pairsPerRow;
    int n   = row & (SEQ - 1);
    int i   = p & 31;
    float freq = expf(-(float)i * (9.2103403719761836f / 32.0f));
    float ph = (float)n * freq;
    float sn, cs;
    sincosf(ph, &sn, &cs);
    float* base = x + (size_t)row * width + 2 * p;
    float x0 = base[0], x1 = base[1];
    base[0] = x0 * cs - x1 * sn;
    base[1] = x0 * sn + x1 * cs;
}

// ---------------- flash attention (fp32) ------------------------------------
__global__ __launch_bounds__(128)
void flash_kernel(const float* __restrict__ q, const float* __restrict__ k,
                  const float* __restrict__ v, float* __restrict__ o) {
    __shared__ float Ks[64][64];
    __shared__ float Vs[64][64];

    const int tid = threadIdx.x;
    const int b = blockIdx.z;
    const int h = blockIdx.y;
    const int kvh = h >> 2;
    const int qi = blockIdx.x * 128 + tid;

    const float* qp = q + (((size_t)b * SEQ + qi) * NH + h) * HD;
    float qreg[64];
    #pragma unroll
    for (int d = 0; d < 64; d += 4) {
        float4 t = *(const float4*)&qp[d];
        qreg[d] = t.x; qreg[d+1] = t.y; qreg[d+2] = t.z; qreg[d+3] = t.w;
    }

    float m = -INFINITY, l = 0.0f;
    float accv[64];
    #pragma unroll
    for (int d = 0; d < 64; d++) accv[d] = 0.0f;

    const int jt_max = blockIdx.x * 2 + 1;
    const int lr   = tid >> 1;
    const int lcol = (tid & 1) * 32;

    for (int jt = 0; jt <= jt_max; jt++) {
        const size_t krow = ((size_t)b * SEQ + jt * 64 + lr) * NKV + kvh;
        const float* kp = k + krow * HD + lcol;
        const float* vp = v + krow * HD + lcol;
        #pragma unroll
        for (int c = 0; c < 32; c += 4) {
            *(float4*)&Ks[lr][lcol + c] = *(const float4*)&kp[c];
            *(float4*)&Vs[lr][lcol + c] = *(const float4*)&vp[c];
        }
        __syncthreads();

        int jmax = qi - jt * 64;
        if (jmax > 63) jmax = 63;
        for (int j = 0; j <= jmax; j++) {
            float s0 = 0.f, s1 = 0.f, s2 = 0.f, s3 = 0.f;
            #pragma unroll
            for (int d = 0; d < 64; d += 4) {
                s0 = fmaf(qreg[d],     Ks[j][d],     s0);
                s1 = fmaf(qreg[d + 1], Ks[j][d + 1], s1);
                s2 = fmaf(qreg[d + 2], Ks[j][d + 2], s2);
                s3 = fmaf(qreg[d + 3], Ks[j][d + 3], s3);
            }
            float s = ((s0 + s1) + (s2 + s3)) * 0.125f;

            float m_new = fmaxf(m, s);
            float corr  = __expf(m - m_new);
            float p     = __expf(s - m_new);
            l = l * corr + p;
            #pragma unroll
            for (int d = 0; d < 64; d++)
                accv[d] = fmaf(accv[d], corr, p * Vs[j][d]);
            m = m_new;
        }
        __syncthreads();
    }

    const float inv = 1.0f / l;
    float* op = o + (((size_t)b * SEQ + qi) * NH + h) * HD;
    #pragma unroll
    for (int d = 0; d < 64; d += 4) {
        float4 t = make_float4(accv[d] * inv, accv[d+1] * inv,
                               accv[d+2] * inv, accv[d+3] * inv);
        *(float4*)&op[d] = t;
    }
}

// ---------------------------------------------------------------------------
extern "C" void kernel_launch(void* const* d_in, const int* in_sizes, int n_in,
                              void* d_out, int out_size) {
    const float* x  = (const float*)d_in[0];
    const float* wq = (const float*)d_in[1];
    const float* wk = (const float*)d_in[2];
    const float* wv = (const float*)d_in[3];
    const float* wo = (const float*)d_in[4];
    float* out = (float*)d_out;

    float *qb, *kb, *vb, *ab;
    cudaGetSymbolAddress((void**)&qb, g_q);
    cudaGetSymbolAddress((void**)&kb, g_k);
    cudaGetSymbolAddress((void**)&vb, g_v);
    cudaGetSymbolAddress((void**)&ab, g_att);

    __nv_bfloat16 *xh, *xl, *ah, *al;
    __nv_bfloat16 *wqh, *wql, *wkh, *wkl, *wvh, *wvl, *woh, *wol;
    cudaGetSymbolAddress((void**)&xh,  g_xh);  cudaGetSymbolAddress((void**)&xl,  g_xl);
    cudaGetSymbolAddress((void**)&ah,  g_ah);  cudaGetSymbolAddress((void**)&al,  g_al);
    cudaGetSymbolAddress((void**)&wqh, g_wqh); cudaGetSymbolAddress((void**)&wql, g_wql);
    cudaGetSymbolAddress((void**)&wkh, g_wkh); cudaGetSymbolAddress((void**)&wkl, g_wkl);
    cudaGetSymbolAddress((void**)&wvh, g_wvh); cudaGetSymbolAddress((void**)&wvl, g_wvl);
    cudaGetSymbolAddress((void**)&woh, g_woh); cudaGetSymbolAddress((void**)&wol, g_wol);

    cudaFuncSetAttribute(mma_gemm, cudaFuncAttributeMaxDynamicSharedMemorySize, GEMM_SMEM);

    const int M = MTOT;   // 2048

    // convert inputs / weights to bf16 hi/lo (weights transposed to [N,K])
    {
        int n = M * DIM_;
        split_bf16<<<(n + 255) / 256, 256>>>(x, xh, xl, n);
        dim3 blk(32, 8);
        transpose_split<<<dim3(DIM_ / 32, DIM_ / 32), blk>>>(wq, wqh, wql, DIM_, DIM_);
        transpose_split<<<dim3(KVD  / 32, DIM_ / 32), blk>>>(wk, wkh, wkl, DIM_, KVD);
        transpose_split<<<dim3(KVD  / 32, DIM_ / 32), blk>>>(wv, wvh, wvl, DIM_, KVD);
        transpose_split<<<dim3(DIM_ / 32, DIM_ / 32), blk>>>(wo, woh, wol, DIM_, DIM_);
    }

    // QKV projections on tensor cores (mma.sync)
    mma_gemm<<<dim3(DIM_ / 128, M / 128), 256, GEMM_SMEM>>>(xh, xl, wqh, wql, qb, DIM_, DIM_);
    mma_gemm<<<dim3(KVD  / 128, M / 128), 256, GEMM_SMEM>>>(xh, xl, wkh, wkl, kb, KVD,  DIM_);
    mma_gemm<<<dim3(KVD  / 128, M / 128), 256, GEMM_SMEM>>>(xh, xl, wvh, wvl, vb, KVD,  DIM_);

    // RoPE
    {
        int totq = M * (DIM_ / 2);
        rope_kernel<<<(totq + 255) / 256, 256>>>(qb, DIM_);
        int totk = M * (KVD / 2);
        rope_kernel<<<(totk + 255) / 256, 256>>>(kb, KVD);
    }

    // causal GQA attention
    flash_kernel<<<dim3(SEQ / 128, NH, B_), 128>>>(qb, kb, vb, ab);

    // convert attention output, then output projection
    {
        int n = M * DIM_;
        split_bf16<<<(n + 255) / 256, 256>>>(ab, ah, al, n);
    }
    mma_gemm<<<dim3(DIM_ / 128, M / 128), 256, GEMM_SMEM>>>(ah, al, woh, wol, out, DIM_, DIM_);
}

// round 6
// speedup vs baseline: 2.9588x; 1.7619x over previous
#include <cuda_runtime.h>
#include <cuda_bf16.h>
#include <math.h>
#include <stdint.h>

#define B_   2
#define SEQ  1024
#define DIM_ 2048
#define KVD  512
#define NH   32
#define NKV  8
#define HD   64
#define MTOT (B_ * SEQ)   // 2048
#define QKVW 3072         // fused q|k|v width

// ---------------- scratch (__device__ globals; allocation-guard safe) ------
__device__ float g_qkv[MTOT * QKVW];
__device__ __nv_bfloat16 g_xh[MTOT * DIM_], g_xl[MTOT * DIM_];
__device__ __nv_bfloat16 g_ah[MTOT * DIM_], g_al[MTOT * DIM_];
// fused transposed weights [3072][2048]: rows 0-2047 = wq^T, 2048-2559 = wk^T, 2560-3071 = wv^T
__device__ __nv_bfloat16 g_wh[QKVW * DIM_], g_wl[QKVW * DIM_];
__device__ __nv_bfloat16 g_woh[DIM_ * DIM_], g_wol[DIM_ * DIM_];

// ---------------- helpers ---------------------------------------------------
__device__ __forceinline__ uint32_t smem_u32(const void* p) {
    uint32_t a;
    asm("{ .reg .u64 t; cvta.to.shared.u64 t, %1; cvt.u32.u64 %0, t; }"
        : "=r"(a) : "l"(p));
    return a;
}
__device__ __forceinline__ void cp16(uint32_t dst, const void* src) {
    uint64_t g = __cvta_generic_to_global(src);
    asm volatile("cp.async.cg.shared.global [%0], [%1], 16;" :: "r"(dst), "l"(g));
}
__device__ __forceinline__ void ldmx4(uint32_t* r, uint32_t addr) {
    asm volatile("ldmatrix.sync.aligned.m8n8.x4.shared.b16 {%0,%1,%2,%3}, [%4];"
                 : "=r"(r[0]), "=r"(r[1]), "=r"(r[2]), "=r"(r[3]) : "r"(addr));
}
__device__ __forceinline__ void mma16816(float* c, const uint32_t* a, const uint32_t* b) {
    asm volatile(
        "mma.sync.aligned.m16n8k16.row.col.f32.bf16.bf16.f32 "
        "{%0,%1,%2,%3}, {%4,%5,%6,%7}, {%8,%9}, {%0,%1,%2,%3};"
        : "+f"(c[0]), "+f"(c[1]), "+f"(c[2]), "+f"(c[3])
        : "r"(a[0]), "r"(a[1]), "r"(a[2]), "r"(a[3]), "r"(b[0]), "r"(b[1]));
}
// split pair (a,b) into packed bf16x2 hi and lo words
__device__ __forceinline__ void split2(float a, float b, uint32_t& hi, uint32_t& lo) {
    __nv_bfloat16 ha = __float2bfloat16(a), hb = __float2bfloat16(b);
    __nv_bfloat16 la = __float2bfloat16(a - __bfloat162float(ha));
    __nv_bfloat16 lb = __float2bfloat16(b - __bfloat162float(hb));
    __nv_bfloat162 th; th.x = ha; th.y = hb;
    __nv_bfloat162 tl; tl.x = la; tl.y = lb;
    hi = *reinterpret_cast<uint32_t*>(&th);
    lo = *reinterpret_cast<uint32_t*>(&tl);
}

// ---------------- conversion kernels ---------------------------------------
__global__ void split_bf16(const float* __restrict__ src,
                           __nv_bfloat16* __restrict__ hi,
                           __nv_bfloat16* __restrict__ lo, int n) {
    int i = blockIdx.x * blockDim.x + threadIdx.x;
    if (i >= n) return;
    float v = src[i];
    __nv_bfloat16 h = __float2bfloat16(v);
    hi[i] = h;
    lo[i] = __float2bfloat16(v - __bfloat162float(h));
}

// W [K,N] row-major -> hi/lo [N,K] row-major (N local to this call)
__global__ void transpose_split(const float* __restrict__ W,
                                __nv_bfloat16* __restrict__ hi,
                                __nv_bfloat16* __restrict__ lo, int K, int N) {
    __shared__ float t[32][33];
    int k0 = blockIdx.y * 32, n0 = blockIdx.x * 32;
    int tx = threadIdx.x, ty = threadIdx.y;   // 32 x 8
    #pragma unroll
    for (int r = ty; r < 32; r += 8)
        t[r][tx] = W[(size_t)(k0 + r) * N + n0 + tx];
    __syncthreads();
    #pragma unroll
    for (int r = ty; r < 32; r += 8) {
        float v = t[tx][r];   // W[k0+tx][n0+r]
        __nv_bfloat16 h = __float2bfloat16(v);
        size_t o = (size_t)(n0 + r) * K + k0 + tx;
        hi[o] = h;
        lo[o] = __float2bfloat16(v - __bfloat162float(h));
    }
}

// ---------------- mma.sync bf16 GEMM (validated R5) --------------------------
#define ROWB       80
#define TILE_B     (128 * ROWB)
#define STAGE_B    (4 * TILE_B)
#define GEMM_SMEM  (2 * STAGE_B)

__global__ __launch_bounds__(256)
void mma_gemm(const __nv_bfloat16* __restrict__ Ah, const __nv_bfloat16* __restrict__ Al,
              const __nv_bfloat16* __restrict__ Bh, const __nv_bfloat16* __restrict__ Bl,
              float* __restrict__ C, int N, int K) {
    extern __shared__ char sm[];
    const uint32_t sbase = smem_u32(sm);
    const int tid  = threadIdx.x;
    const int wid  = tid >> 5;
    const int lane = tid & 31;
    const int wm = wid & 3;
    const int wn = wid >> 2;
    const int m0 = blockIdx.y * 128, n0 = blockIdx.x * 128;

    float acc[2][8][4];
    #pragma unroll
    for (int i = 0; i < 2; i++)
        #pragma unroll
        for (int j = 0; j < 8; j++)
            #pragma unroll
            for (int q = 0; q < 4; q++) acc[i][j][q] = 0.0f;

    const __nv_bfloat16* base[4] = {
        Ah + (size_t)m0 * K, Al + (size_t)m0 * K,
        Bh + (size_t)n0 * K, Bl + (size_t)n0 * K };

    const int r0 = tid >> 2, c0 = tid & 3;
    const int r1 = (tid + 256) >> 2, c1 = tid & 3;

    auto load_stage = [&](int cidx) {
        const int k0 = cidx << 5;
        const uint32_t db = sbase + (uint32_t)(cidx & 1) * STAGE_B;
        #pragma unroll
        for (int t = 0; t < 4; t++) {
            const uint32_t tb = db + t * TILE_B;
            cp16(tb + r0 * ROWB + c0 * 16, base[t] + (size_t)r0 * K + k0 + c0 * 8);
            cp16(tb + r1 * ROWB + c1 * 16, base[t] + (size_t)r1 * K + k0 + c1 * 8);
        }
        asm volatile("cp.async.commit_group;");
    };

    const int aRow  = lane & 15;
    const uint32_t aColb = (uint32_t)(lane >> 4) * 16;
    const int bRow  = ((lane & 16) >> 1) + (lane & 7);
    const uint32_t bColb = (uint32_t)((lane >> 3) & 1) * 16;

    load_stage(0);
    const int NC = K >> 5;
    for (int c = 0; c < NC; c++) {
        if (c + 1 < NC) {
            load_stage(c + 1);
            asm volatile("cp.async.wait_group 1;");
        } else {
            asm volatile("cp.async.wait_group 0;");
        }
        __syncthreads();

        const uint32_t db = sbase + (uint32_t)(c & 1) * STAGE_B;
        #pragma unroll
        for (int ks = 0; ks < 2; ks++) {
            const uint32_t kb = (uint32_t)ks * 32;
            uint32_t ah[2][4], al[2][4];
            #pragma unroll
            for (int mt = 0; mt < 2; mt++) {
                uint32_t addr = db + (uint32_t)(wm * 32 + mt * 16 + aRow) * ROWB + aColb + kb;
                ldmx4(ah[mt], addr);
                ldmx4(al[mt], addr + TILE_B);
            }
            uint32_t bh[4][4], bl[4][4];
            #pragma unroll
            for (int ng = 0; ng < 4; ng++) {
                uint32_t addr = db + 2 * TILE_B +
                                (uint32_t)(wn * 64 + ng * 16 + bRow) * ROWB + bColb + kb;
                ldmx4(bh[ng], addr);
                ldmx4(bl[ng], addr + TILE_B);
            }
            #pragma unroll
            for (int mt = 0; mt < 2; mt++)
                #pragma unroll
                for (int nt = 0; nt < 8; nt++) {
                    const int ng = nt >> 1, hf = (nt & 1) * 2;
                    mma16816(acc[mt][nt], ah[mt], &bh[ng][hf]);
                    mma16816(acc[mt][nt], ah[mt], &bl[ng][hf]);
                    mma16816(acc[mt][nt], al[mt], &bh[ng][hf]);
                }
        }
        __syncthreads();
    }

    const int g = lane >> 2, tg = lane & 3;
    #pragma unroll
    for (int mt = 0; mt < 2; mt++)
        #pragma unroll
        for (int nt = 0; nt < 8; nt++) {
            const int row = m0 + wm * 32 + mt * 16 + g;
            const int col = n0 + wn * 64 + nt * 8 + tg * 2;
            *(float2*)&C[(size_t)row * N + col] =
                make_float2(acc[mt][nt][0], acc[mt][nt][1]);
            *(float2*)&C[(size_t)(row + 8) * N + col] =
                make_float2(acc[mt][nt][2], acc[mt][nt][3]);
        }
}

// ---------------- RoPE (strided view) ---------------------------------------
__global__ void rope2(float* __restrict__ x, int width, int stride) {
    const int pairsPerRow = width >> 1;
    int idx = blockIdx.x * blockDim.x + threadIdx.x;
    int total = MTOT * pairsPerRow;
    if (idx >= total) return;
    int row = idx / pairsPerRow;
    int p   = idx - row * pairsPerRow;
    int n   = row & (SEQ - 1);
    int i   = p & 31;
    float freq = expf(-(float)i * (9.2103403719761836f / 32.0f));
    float ph = (float)n * freq;
    float sn, cs;
    sincosf(ph, &sn, &cs);
    float* base = x + (size_t)row * stride + 2 * p;
    float x0 = base[0], x1 = base[1];
    base[0] = x0 * cs - x1 * sn;
    base[1] = x0 * sn + x1 * cs;
}

// ---------------- tensor-core flash attention --------------------------------
// block = 128 thr (4 warps), tile = 64 queries x 64 dim, key tiles of 64.
// smem: Qh Ql Kh Kl VTh VTl, each 64 rows x 144B stride.
#define SR 144
#define TSZ (64 * SR)            // 9216
#define FLASH_SMEM (6 * TSZ)     // 55296

__global__ __launch_bounds__(128)
void flash_tc(const float* __restrict__ qkv,
              __nv_bfloat16* __restrict__ oh, __nv_bfloat16* __restrict__ ol) {
    extern __shared__ char sm[];
    const uint32_t sb = smem_u32(sm);
    const int tid = threadIdx.x, w = tid >> 5, lane = tid & 31;
    const int qt = blockIdx.x, h = blockIdx.y, b = blockIdx.z, kvh = h >> 2;
    const int q0 = qt * 64;
    const int oQh = 0, oQl = TSZ, oKh = 2*TSZ, oKl = 3*TSZ, oVh = 4*TSZ, oVl = 5*TSZ;

    // ---- load Q tile (scaled by 1/sqrt(hd)=0.125), split hi/lo ----
    {
        int r = tid >> 1, dh = (tid & 1) * 32;
        const float* src = qkv + ((size_t)(b * SEQ + q0 + r)) * QKVW + h * 64 + dh;
        #pragma unroll
        for (int j = 0; j < 8; j++) {
            float4 v = *(const float4*)(src + j * 4);
            v.x *= 0.125f; v.y *= 0.125f; v.z *= 0.125f; v.w *= 0.125f;
            uint32_t h01, l01, h23, l23;
            split2(v.x, v.y, h01, l01);
            split2(v.z, v.w, h23, l23);
            int off = r * SR + (dh + j * 4) * 2;
            *(uint2*)(sm + oQh + off) = make_uint2(h01, h23);
            *(uint2*)(sm + oQl + off) = make_uint2(l01, l23);
        }
    }
    __syncthreads();

    // Q A-fragments (per warp: rows w*16..w*16+15, 4 k-steps over d)
    uint32_t qah[4][4], qal[4][4];
    {
        int aRow = lane & 15;
        uint32_t aCol = (uint32_t)(lane >> 4) * 16;
        #pragma unroll
        for (int ks = 0; ks < 4; ks++) {
            uint32_t ad = sb + oQh + (uint32_t)(w * 16 + aRow) * SR + aCol + ks * 32;
            ldmx4(qah[ks], ad);
            ldmx4(qal[ks], ad + TSZ);
        }
    }

    const int bRow = ((lane & 16) >> 1) | (lane & 7);
    const uint32_t bCol = (uint32_t)((lane >> 3) & 1) * 16;
    const int g = lane >> 2, tg = lane & 3;

    float oacc[8][4];
    #pragma unroll
    for (int nt = 0; nt < 8; nt++)
        #pragma unroll
        for (int q = 0; q < 4; q++) oacc[nt][q] = 0.0f;
    float m0v = -INFINITY, m1v = -INFINITY, l0v = 0.0f, l1v = 0.0f;

    for (int kt = 0; kt <= qt; kt++) {
        __syncthreads();   // protect smem K/V from previous iteration's readers
        // ---- load K,V tile; K -> [key][d], V -> transposed [d][key] ----
        {
            int r = tid >> 1, dh = (tid & 1) * 32;
            const float* ksrc = qkv + ((size_t)(b * SEQ + kt * 64 + r)) * QKVW
                                + DIM_ + kvh * 64 + dh;
            const float* vsrc = ksrc + KVD;
            #pragma unroll
            for (int j = 0; j < 8; j++) {
                float4 kv = *(const float4*)(ksrc + j * 4);
                uint32_t h01, l01, h23, l23;
                split2(kv.x, kv.y, h01, l01);
                split2(kv.z, kv.w, h23, l23);
                int off = r * SR + (dh + j * 4) * 2;
                *(uint2*)(sm + oKh + off) = make_uint2(h01, h23);
                *(uint2*)(sm + oKl + off) = make_uint2(l01, l23);

                float4 vv = *(const float4*)(vsrc + j * 4);
                float fe[4] = { vv.x, vv.y, vv.z, vv.w };
                #pragma unroll
                for (int e = 0; e < 4; e++) {
                    __nv_bfloat16 hb = __float2bfloat16(fe[e]);
                    __nv_bfloat16 lb = __float2bfloat16(fe[e] - __bfloat162float(hb));
                    int d = dh + j * 4 + e;
                    *(__nv_bfloat16*)(sm + oVh + d * SR + r * 2) = hb;
                    *(__nv_bfloat16*)(sm + oVl + d * SR + r * 2) = lb;
                }
            }
        }
        __syncthreads();

        // ---- S = Q @ K^T (hi/lo 3-product) ----
        float sacc[8][4];
        #pragma unroll
        for (int nt = 0; nt < 8; nt++)
            #pragma unroll
            for (int q = 0; q < 4; q++) sacc[nt][q] = 0.0f;

        #pragma unroll
        for (int ks = 0; ks < 4; ks++) {
            uint32_t kbh[4][4], kbl[4][4];
            #pragma unroll
            for (int ng = 0; ng < 4; ng++) {
                uint32_t adr = sb + oKh + (uint32_t)(ng * 16 + bRow) * SR + bCol + ks * 32;
                ldmx4(kbh[ng], adr);
                ldmx4(kbl[ng], adr + TSZ);
            }
            #pragma unroll
            for (int nt = 0; nt < 8; nt++) {
                const int ng = nt >> 1, hf = (nt & 1) * 2;
                mma16816(sacc[nt], qah[ks], &kbh[ng][hf]);
                mma16816(sacc[nt], qah[ks], &kbl[ng][hf]);
                mma16816(sacc[nt], qal[ks], &kbh[ng][hf]);
            }
        }

        // ---- causal mask (diagonal tile only) ----
        if (kt == qt) {
            int r0 = w * 16 + g, r1 = r0 + 8;
            #pragma unroll
            for (int nt = 0; nt < 8; nt++) {
                int c0 = nt * 8 + tg * 2;
                if (c0     > r0) sacc[nt][0] = -1e30f;
                if (c0 + 1 > r0) sacc[nt][1] = -1e30f;
                if (c0     > r1) sacc[nt][2] = -1e30f;
                if (c0 + 1 > r1) sacc[nt][3] = -1e30f;
            }
        }

        // ---- online softmax ----
        float mx0 = -INFINITY, mx1 = -INFINITY;
        #pragma unroll
        for (int nt = 0; nt < 8; nt++) {
            mx0 = fmaxf(mx0, fmaxf(sacc[nt][0], sacc[nt][1]));
            mx1 = fmaxf(mx1, fmaxf(sacc[nt][2], sacc[nt][3]));
        }
        mx0 = fmaxf(mx0, __shfl_xor_sync(0xffffffffu, mx0, 1));
        mx0 = fmaxf(mx0, __shfl_xor_sync(0xffffffffu, mx0, 2));
        mx1 = fmaxf(mx1, __shfl_xor_sync(0xffffffffu, mx1, 1));
        mx1 = fmaxf(mx1, __shfl_xor_sync(0xffffffffu, mx1, 2));

        float mn0 = fmaxf(m0v, mx0), mn1 = fmaxf(m1v, mx1);
        float cr0 = __expf(m0v - mn0), cr1 = __expf(m1v - mn1);
        m0v = mn0; m1v = mn1;
        l0v *= cr0; l1v *= cr1;
        #pragma unroll
        for (int nt = 0; nt < 8; nt++) {
            oacc[nt][0] *= cr0; oacc[nt][1] *= cr0;
            oacc[nt][2] *= cr1; oacc[nt][3] *= cr1;
        }
        float rs0 = 0.0f, rs1 = 0.0f;

        // ---- P = exp(S-m); O += P @ V (hi/lo 3-product), fused per k-step ----
        #pragma unroll
        for (int ks = 0; ks < 4; ks++) {
            float p[2][4];
            #pragma unroll
            for (int jj = 0; jj < 2; jj++) {
                const int nt = 2 * ks + jj;
                p[jj][0] = __expf(sacc[nt][0] - mn0);
                p[jj][1] = __expf(sacc[nt][1] - mn0);
                p[jj][2] = __expf(sacc[nt][2] - mn1);
                p[jj][3] = __expf(sacc[nt][3] - mn1);
                rs0 += p[jj][0] + p[jj][1];
                rs1 += p[jj][2] + p[jj][3];
            }
            uint32_t pah[4], pal[4];
            split2(p[0][0], p[0][1], pah[0], pal[0]);
            split2(p[0][2], p[0][3], pah[1], pal[1]);
            split2(p[1][0], p[1][1], pah[2], pal[2]);
            split2(p[1][2], p[1][3], pah[3], pal[3]);

            uint32_t vbh[4][4], vbl[4][4];
            #pragma unroll
            for (int ng = 0; ng < 4; ng++) {
                uint32_t adr = sb + oVh + (uint32_t)(ng * 16 + bRow) * SR + bCol + ks * 32;
                ldmx4(vbh[ng], adr);
                ldmx4(vbl[ng], adr + TSZ);
            }
            #pragma unroll
            for (int nt = 0; nt < 8; nt++) {
                const int ng = nt >> 1, hf = (nt & 1) * 2;
                mma16816(oacc[nt], pah, &vbh[ng][hf]);
                mma16816(oacc[nt], pah, &vbl[ng][hf]);
                mma16816(oacc[nt], pal, &vbh[ng][hf]);
            }
        }
        rs0 += __shfl_xor_sync(0xffffffffu, rs0, 1);
        rs0 += __shfl_xor_sync(0xffffffffu, rs0, 2);
        rs1 += __shfl_xor_sync(0xffffffffu, rs1, 1);
        rs1 += __shfl_xor_sync(0xffffffffu, rs1, 2);
        l0v += rs0; l1v += rs1;
    }

    // ---- epilogue: normalize, split to bf16 hi/lo, store ----
    const float i0 = 1.0f / l0v, i1 = 1.0f / l1v;
    const int r0 = q0 + w * 16 + g;
    #pragma unroll
    for (int nt = 0; nt < 8; nt++) {
        const int col = h * 64 + nt * 8 + tg * 2;
        const size_t o0 = ((size_t)(b * SEQ + r0)) * DIM_ + col;
        const size_t o1 = o0 + (size_t)8 * DIM_;
        uint32_t H, L;
        split2(oacc[nt][0] * i0, oacc[nt][1] * i0, H, L);
        *(uint32_t*)&oh[o0] = H;
        *(uint32_t*)&ol[o0] = L;
        split2(oacc[nt][2] * i1, oacc[nt][3] * i1, H, L);
        *(uint32_t*)&oh[o1] = H;
        *(uint32_t*)&ol[o1] = L;
    }
}

// ---------------------------------------------------------------------------
extern "C" void kernel_launch(void* const* d_in, const int* in_sizes, int n_in,
                              void* d_out, int out_size) {
    const float* x  = (const float*)d_in[0];
    const float* wq = (const float*)d_in[1];
    const float* wk = (const float*)d_in[2];
    const float* wv = (const float*)d_in[3];
    const float* wo = (const float*)d_in[4];
    float* out = (float*)d_out;

    float* qkv;
    cudaGetSymbolAddress((void**)&qkv, g_qkv);
    __nv_bfloat16 *xh, *xl, *ah, *al, *wh, *wl, *woh, *wol;
    cudaGetSymbolAddress((void**)&xh,  g_xh);  cudaGetSymbolAddress((void**)&xl,  g_xl);
    cudaGetSymbolAddress((void**)&ah,  g_ah);  cudaGetSymbolAddress((void**)&al,  g_al);
    cudaGetSymbolAddress((void**)&wh,  g_wh);  cudaGetSymbolAddress((void**)&wl,  g_wl);
    cudaGetSymbolAddress((void**)&woh, g_woh); cudaGetSymbolAddress((void**)&wol, g_wol);

    cudaFuncSetAttribute(mma_gemm, cudaFuncAttributeMaxDynamicSharedMemorySize, GEMM_SMEM);
    cudaFuncSetAttribute(flash_tc, cudaFuncAttributeMaxDynamicSharedMemorySize, FLASH_SMEM);

    const int M = MTOT;

    // ---- convert input + weights (fused transposed weight buffer) ----
    {
        int n = M * DIM_;
        split_bf16<<<(n + 255) / 256, 256>>>(x, xh, xl, n);
        dim3 blk(32, 8);
        transpose_split<<<dim3(DIM_ / 32, DIM_ / 32), blk>>>(
            wq, wh, wl, DIM_, DIM_);
        transpose_split<<<dim3(KVD / 32, DIM_ / 32), blk>>>(
            wk, wh + (size_t)DIM_ * DIM_, wl + (size_t)DIM_ * DIM_, DIM_, KVD);
        transpose_split<<<dim3(KVD / 32, DIM_ / 32), blk>>>(
            wv, wh + (size_t)(DIM_ + KVD) * DIM_, wl + (size_t)(DIM_ + KVD) * DIM_, DIM_, KVD);
        transpose_split<<<dim3(DIM_ / 32, DIM_ / 32), blk>>>(
            wo, woh, wol, DIM_, DIM_);
    }

    // ---- fused QKV projection ----
    mma_gemm<<<dim3(QKVW / 128, M / 128), 256, GEMM_SMEM>>>(xh, xl, wh, wl, qkv, QKVW, DIM_);

    // ---- RoPE on q and k sections ----
    rope2<<<(M * (DIM_ / 2) + 255) / 256, 256>>>(qkv, DIM_, QKVW);
    rope2<<<(M * (KVD  / 2) + 255) / 256, 256>>>(qkv + DIM_, KVD, QKVW);

    // ---- tensor-core causal GQA flash attention (writes bf16 hi/lo) ----
    flash_tc<<<dim3(SEQ / 64, NH, B_), 128, FLASH_SMEM>>>(qkv, ah, al);

    // ---- output projection ----
    mma_gemm<<<dim3(DIM_ / 128, M / 128), 256, GEMM_SMEM>>>(ah, al, woh, wol, out, DIM_, DIM_);
}